// round 8
// baseline (speedup 1.0000x reference)
#include <cuda_runtime.h>
#include <cuda_bf16.h>
#include <cstdint>

#define NB      1024
#define NNODES  10000
#define NROOTS  4
#define MNODES  (NNODES - NROOTS)   // 9996
#define NCONF   16
#define NRG     32
#define NPAD    10016

// Transposed bit-pack, rg-major: g_evt[rg*NPAD + n] bit r = ev[rg*32+r][n]
__device__ uint32_t g_evt[NRG * NPAD];       // 1.28 MB
__device__ float    g_sig[MNODES * NCONF];   // 640 KB pre-sigmoided CPT

// ---------------------------------------------------------------------------
// Kernel A (fused pack + sigmoid). Pack: warp tile = 64 nodes x 32 rows.
// Lane owns 2 nodes; register bit-accumulate from 32 coalesced int2 loads.
// ---------------------------------------------------------------------------
#define PACK_TILES   157                    // ceil(10000/64)
#define PACK_BLOCKS  (PACK_TILES * 32 / 8)  // 628
#define SIG_TOTAL    (MNODES * NCONF / 4)   // 39984 float4
#define SIG_BLOCKS   ((SIG_TOTAL + 255) / 256)

__global__ __launch_bounds__(256)
void pack_sig_kernel(const int* __restrict__ ev, const float4* __restrict__ cpt4) {
    if (blockIdx.x >= PACK_BLOCKS) {
        int idx = (blockIdx.x - PACK_BLOCKS) * 256 + threadIdx.x;
        if (idx < SIG_TOTAL) {
            float4 x = cpt4[idx];
            float4 y;
            y.x = 1.0f / (1.0f + __expf(-x.x));
            y.y = 1.0f / (1.0f + __expf(-x.y));
            y.z = 1.0f / (1.0f + __expf(-x.z));
            y.w = 1.0f / (1.0f + __expf(-x.w));
            ((float4*)g_sig)[idx] = y;
        }
        return;
    }

    const int g    = blockIdx.x * 8 + (threadIdx.x >> 5);
    const int lane = threadIdx.x & 31;
    const int rg   = g & 31;
    const int tile = g >> 5;                 // 0..156
    const int n    = tile * 64 + lane * 2;
    if (n >= NNODES) return;                 // NNODES even: pairs never straddle

    const int* __restrict__ base = ev + (size_t)(rg * 32) * NNODES + n;
    uint32_t a0 = 0, a1 = 0;
    #pragma unroll 8
    for (int r = 0; r < 32; r++) {
        int2 v = *(const int2*)(base + (size_t)r * NNODES);
        a0 |= (uint32_t)(v.x & 1) << r;
        a1 |= (uint32_t)(v.y & 1) << r;
    }
    *(uint2*)(g_evt + rg * NPAD + n) = make_uint2(a0, a1);
}

// ---------------------------------------------------------------------------
// Kernel B: main. grid=(20, 32), block=256. Thread owns node PAIR (2*ip,
// 2*ip+1) for one 32-row group: 8 evt word gathers, 32 sigmoids staged
// conf-major (conflict-free), hot loop = 2 LDS + 1 STG.64 per row.
// ---------------------------------------------------------------------------
#define THREADS 256

__global__ __launch_bounds__(THREADS)
void bayes_main(const int4*  __restrict__ parents4,
                const float* __restrict__ root_logits,
                float*       __restrict__ out) {
    __shared__ float slot[NCONF * 2 * THREADS];        // 32 KB

    const int rg  = blockIdx.y;
    const int b0  = rg * 32;
    const int tid = threadIdx.x;
    const int ip  = blockIdx.x * THREADS + tid;        // node-pair index
    const int i0  = ip * 2;

    if (blockIdx.x == 0 && tid < 32 * NROOTS) {
        int r = tid & (NROOTS - 1), row = tid >> 2;
        float x = root_logits[r];
        out[(size_t)(b0 + row) * NNODES + r] = 1.0f / (1.0f + __expf(-x));
    }
    if (i0 >= MNODES) return;

    const uint32_t* __restrict__ evt = g_evt + rg * NPAD;
    const int4 pa = parents4[i0];
    const int4 pb = parents4[i0 + 1];
    const uint32_t w0 = evt[pa.x], w1 = evt[pa.y], w2 = evt[pa.z], w3 = evt[pa.w];
    const uint32_t v0 = evt[pb.x], v1 = evt[pb.y], v2 = evt[pb.z], v3 = evt[pb.w];

    // Stage 2x16 pre-sigmoided values conf-major: slot[(c*2+node)*T + tid]
    {
        const float4* __restrict__ s0 = (const float4*)(g_sig + (size_t)i0 * NCONF);
        #pragma unroll
        for (int j = 0; j < 4; j++) {
            float4 a = s0[j];                          // node 0, confs 4j..4j+3
            slot[((4 * j + 0) * 2 + 0) * THREADS + tid] = a.x;
            slot[((4 * j + 1) * 2 + 0) * THREADS + tid] = a.y;
            slot[((4 * j + 2) * 2 + 0) * THREADS + tid] = a.z;
            slot[((4 * j + 3) * 2 + 0) * THREADS + tid] = a.w;
            float4 b = s0[4 + j];                      // node 1
            slot[((4 * j + 0) * 2 + 1) * THREADS + tid] = b.x;
            slot[((4 * j + 1) * 2 + 1) * THREADS + tid] = b.y;
            slot[((4 * j + 2) * 2 + 1) * THREADS + tid] = b.z;
            slot[((4 * j + 3) * 2 + 1) * THREADS + tid] = b.w;
        }
    }

    float* obase = out + (size_t)b0 * NNODES + NROOTS + i0;
    #pragma unroll
    for (int r = 0; r < 32; r++) {
        unsigned c0 = (((w0 >> r) & 1u) << 3)
                    | (((w1 >> r) & 1u) << 2)
                    | (((w2 >> r) & 1u) << 1)
                    |  ((w3 >> r) & 1u);
        unsigned c1 = (((v0 >> r) & 1u) << 3)
                    | (((v1 >> r) & 1u) << 2)
                    | (((v2 >> r) & 1u) << 1)
                    |  ((v3 >> r) & 1u);
        float f0 = slot[(c0 * 2 + 0) * THREADS + tid]; // bank = tid%32
        float f1 = slot[(c1 * 2 + 1) * THREADS + tid];
        *(float2*)(obase + (size_t)r * NNODES) = make_float2(f0, f1); // STG.64
    }
}

// ---------------------------------------------------------------------------
extern "C" void kernel_launch(void* const* d_in, const int* in_sizes, int n_in,
                              void* d_out, int out_size) {
    const int*    ev      = (const int*)d_in[0];
    const int4*   parents = (const int4*)d_in[1];
    const float*  roots   = (const float*)d_in[2];
    const float4* cpt4    = (const float4*)d_in[3];
    float*        out     = (float*)d_out;

    pack_sig_kernel<<<PACK_BLOCKS + SIG_BLOCKS, 256>>>(ev, cpt4);

    dim3 gmain((MNODES / 2 + THREADS - 1) / THREADS, NRG);  // (20, 32)
    bayes_main<<<gmain, THREADS>>>(parents, roots, out);
}